// round 10
// baseline (speedup 1.0000x reference)
#include <cuda_runtime.h>
#include <cuda_fp16.h>
#include <cstdint>
#include <math.h>

#define Bn 2048
#define Ln 128
#define Cn 150
#define Hn 230

// X tile: fp16 padded rows (130 x 168 halves), row stride 336B
#define XRS   168
#define XROWB 336
#define XBUF  (130*XROWB)        // 43,680 B
// W: [hh][128 n][488 k] fp16, k = tap*160 + c
#define WRS   488
#define WROWB 976
#define WTILE (128*WROWB)        // 124,928 B

#define THREADS 640              // 16 GEMM warps + 4 producer warps

// smem layout
#define MB_W    0
#define SM_WC   16               // int wcnt[2][4]
#define SM_ACT  64               // uint8 act[2][128]
#define SM_PMS  320              // uint8 pms[2][128]
#define SM_RED  1024             // float red[4][128][3] = 6144B
#define SM_W    8192
#define SM_X0   (SM_W + WTILE)   // 133,120
#define SM_X1   (SM_X0 + XBUF)   // 176,800
#define SMEM_BYTES (SM_X1 + XBUF) // 220,480

__device__ __align__(128) __half Wg[2 * 128 * WRS];

__global__ void wprep(const float* __restrict__ W) {
    int idx = blockIdx.x * blockDim.x + threadIdx.x;   // 2*128*488
    if (idx >= 2 * 128 * WRS) return;
    int k  = idx % WRS;
    int n  = (idx / WRS) % 128;
    int hh = idx / (WRS * 128);
    int h  = hh * 128 + n;
    int tap = k / 160, c = k - tap * 160;
    float v = (h < Hn && tap < 3 && c < Cn) ? W[((size_t)h * Cn + c) * 3 + tap] : 0.f;
    Wg[idx] = __float2half(v);
}

// ---------------- helpers ----------------
__device__ __forceinline__ void ldsm4(uint32_t* r, uint32_t a) {
    asm volatile("ldmatrix.sync.aligned.m8n8.x4.shared.b16 {%0,%1,%2,%3}, [%4];"
                 : "=r"(r[0]), "=r"(r[1]), "=r"(r[2]), "=r"(r[3]) : "r"(a));
}
__device__ __forceinline__ void mma16816(float* d, const uint32_t* a,
                                         uint32_t b0, uint32_t b1) {
    asm volatile(
        "mma.sync.aligned.m16n8k16.row.col.f32.f16.f16.f32 "
        "{%0,%1,%2,%3},{%4,%5,%6,%7},{%8,%9},{%0,%1,%2,%3};"
        : "+f"(d[0]), "+f"(d[1]), "+f"(d[2]), "+f"(d[3])
        : "r"(a[0]), "r"(a[1]), "r"(a[2]), "r"(a[3]), "r"(b0), "r"(b1));
}
__device__ __forceinline__ void mbar_wait(uint32_t addr, uint32_t parity) {
    asm volatile(
        "{\n\t.reg .pred P;\n\t"
        "W_%=:\n\t"
        "mbarrier.try_wait.parity.acquire.cta.shared::cta.b64 P, [%0], %1;\n\t"
        "@!P bra W_%=;\n\t}"
        :: "r"(addr), "r"(parity) : "memory");
}

// GEMM k-loop, m32n32 warp tile, single-stage; MT = active m16 tiles (1..2)
template<int MT>
__device__ __forceinline__ void gemm_run(uint32_t A0, uint32_t A1, uint32_t boff,
                                         float (*d)[4][4]) {
#pragma unroll
    for (int kk = 0; kk < 30; ++kk) {
        const int tap = kk / 10, kc = kk % 10;
        const uint32_t ka = (uint32_t)(tap * XROWB + kc * 32);
        const uint32_t kb = (uint32_t)(tap * 320 + kc * 32);
        uint32_t a0[4], a1[4], bf[8];
        ldsm4(a0, A0 + ka);
        if (MT == 2) ldsm4(a1, A1 + ka);
        ldsm4(&bf[0], boff + kb);
        ldsm4(&bf[4], boff + 16 * WROWB + kb);
#pragma unroll
        for (int pp = 0; pp < 2; ++pp) {
            mma16816(d[0][2*pp],     a0, bf[pp*4],   bf[pp*4+1]);
            mma16816(d[0][2*pp + 1], a0, bf[pp*4+2], bf[pp*4+3]);
            if (MT == 2) {
                mma16816(d[1][2*pp],     a1, bf[pp*4],   bf[pp*4+1]);
                mma16816(d[1][2*pp + 1], a1, bf[pp*4+2], bf[pp*4+3]);
            }
        }
    }
}

// producer warps: stage fp32 X -> fp16 tile, compact mask (slot-double-buffered)
__device__ __forceinline__ void stage_unit(char* smem, const float* __restrict__ Xea,
                                           const int* __restrict__ Xmask,
                                           int b1, int slot, int t2) {
    char* xbuf = smem + SM_X0 + slot * XBUF;
    const float4* src = (const float4*)(Xea + (size_t)b1 * 19200);
#pragma unroll 1
    for (int base = 0; base < 4800; base += 1024) {
        float4 s[8];
#pragma unroll
        for (int i = 0; i < 8; ++i) {
            int f = base + t2 + 128 * i;
            if (f < 4800) s[i] = __ldg(src + f);
        }
#pragma unroll
        for (int i = 0; i < 8; ++i) {
            int f = base + t2 + 128 * i;
            if (f < 4800) {
                int idx = 4 * f;
                int r = idx / 150;
                int c = idx - 150 * r;
                __half2 p0 = __floats2half2_rn(s[i].x, s[i].y);
                __half2 p1 = __floats2half2_rn(s[i].z, s[i].w);
                *(__half2*)(xbuf + (r + 1) * XROWB + c * 2) = p0;
                int c2 = c + 2, r2 = r;
                if (c2 >= 150) { c2 -= 150; r2 += 1; }
                *(__half2*)(xbuf + (r2 + 1) * XROWB + c2 * 2) = p1;
            }
        }
    }
    // mask compaction
    int mk = Xmask[b1 * Ln + t2];
    unsigned bal = __ballot_sync(0xffffffffu, mk != 0);
    int* wc = (int*)(smem + SM_WC) + slot * 4;
    if ((t2 & 31) == 0) wc[t2 >> 5] = __popc(bal);
    asm volatile("bar.sync 2, 128;" ::: "memory");
    int c0 = wc[0], c1 = wc[1], c2 = wc[2], c3 = wc[3];
    int na = c0 + c1 + c2 + c3;
    uint8_t* act = (uint8_t*)(smem + SM_ACT) + slot * 128;
    uint8_t* pms = (uint8_t*)(smem + SM_PMS) + slot * 128;
    int wofs = (t2 >= 32 ? c0 : 0) + (t2 >= 64 ? c1 : 0) + (t2 >= 96 ? c2 : 0);
    if (mk != 0) {
        int r = wofs + __popc(bal & ((1u << (t2 & 31)) - 1u));
        act[r] = (uint8_t)t2;
        pms[r] = (uint8_t)mk;
    }
    if (t2 >= na) { act[t2] = 0; pms[t2] = 0; }
}

// ---------------- main: grid (2 h-halves, 74), 640 threads ----------------
__global__ __launch_bounds__(THREADS, 1)
void pcnn_mma_kernel(const float* __restrict__ Xea,
                     const int*   __restrict__ Xmask,
                     const float* __restrict__ bias,
                     float*       __restrict__ out)
{
    extern __shared__ char smem[];
    uint32_t sb;
    asm("{ .reg .u64 t; cvta.to.shared.u64 t, %1; cvt.u32.u64 %0, t; }"
        : "=r"(sb) : "l"(smem));
    const int t    = threadIdx.x;
    const int w    = t >> 5, lane = t & 31;
    const int hh   = blockIdx.x;
    const int y    = blockIdx.y;
    const int nh   = w >> 2;                      // n32 chunk (GEMM warps 0..15)
    const int mq   = ((w & 3) + nh) & 3;          // m32 chunk (Latin square vs SMSP)

    if (t == 0) {
        asm volatile("mbarrier.init.shared.b64 [%0], 1;" :: "r"(sb + MB_W) : "memory");
    }
    __syncthreads();
    if (t == 0) {
        asm volatile("mbarrier.arrive.expect_tx.shared.b64 _, [%0], %1;"
                     :: "r"(sb + MB_W), "r"((uint32_t)WTILE) : "memory");
        asm volatile(
            "cp.async.bulk.shared::cluster.global.mbarrier::complete_tx::bytes "
            "[%0], [%1], %2, [%3];"
            :: "r"(sb + SM_W), "l"(Wg + (size_t)hh * 128 * WRS),
               "r"((uint32_t)WTILE), "r"(sb + MB_W) : "memory");
    }

    // zero both X buffers (halo rows + col padding stay zero forever)
    for (int i = t * 16; i < 2 * XBUF; i += THREADS * 16)
        *(uint4*)(smem + SM_X0 + i) = make_uint4(0, 0, 0, 0);
    __syncthreads();

    const int NB = (Bn - y + 73) / 74;

    // bootstrap: producers stage unit 0; GEMM warps wait for W
    if (w >= 16) {
        stage_unit(smem, Xea, Xmask, y, 0, t - 512);
    } else {
        mbar_wait(sb + MB_W, 0);
    }
    __syncthreads();

    // GEMM-warp invariants
    const uint32_t boff = sb + SM_W
        + (uint32_t)((nh * 32 + (lane & 7) + ((lane >> 4) << 3)) * WROWB)
        + (uint32_t)(((lane >> 3) & 1) * 16);
    const uint32_t colp = (uint32_t)((lane >> 4) << 4);
    float bb = 0.f;
    int   hok = 0;
    if (t < 128) {
        int h = hh * 128 + t;
        hok = (h < Hn);
        if (hok) bb = bias[h];
    }

    for (int u = 0; u < NB; ++u) {
        const int buf = u & 1;
        const int b   = y + 74 * u;

        if (w < 16) {
            // ---- consumer: GEMM over compacted rows ----
            const int* wc = (const int*)(smem + SM_WC) + buf * 4;
            const int na = wc[0] + wc[1] + wc[2] + wc[3];
            const uint8_t* act = (const uint8_t*)(smem + SM_ACT) + buf * 128;
            const uint8_t* pms = (const uint8_t*)(smem + SM_PMS) + buf * 128;

            float d[2][4][4];
#pragma unroll
            for (int i = 0; i < 2; ++i)
#pragma unroll
                for (int j = 0; j < 4; ++j)
#pragma unroll
                    for (int e = 0; e < 4; ++e) d[i][j][e] = 0.f;

            const uint32_t xb = sb + SM_X0 + buf * XBUF;
            const uint32_t A0 = xb + (uint32_t)act[mq * 32 + (lane & 15)]      * XROWB + colp;
            const uint32_t A1 = xb + (uint32_t)act[mq * 32 + 16 + (lane & 15)] * XROWB + colp;

            int myrows = na - mq * 32;
            if (myrows > 32) myrows = 32;
            if (myrows > 16)     gemm_run<2>(A0, A1, boff, d);
            else if (myrows > 0) gemm_run<1>(A0, A1, boff, d);

            // ---- register epilogue: mask-gated max ----
            float pm[3][8];
#pragma unroll
            for (int m = 0; m < 3; ++m)
#pragma unroll
                for (int c = 0; c < 8; ++c) pm[m][c] = -INFINITY;

            const int rb = mq * 32 + (lane >> 2);
#pragma unroll
            for (int mt = 0; mt < 2; ++mt) {
                int mk0 = pms[rb + mt * 16];
                int mk1 = pms[rb + mt * 16 + 8];
#pragma unroll
                for (int j = 0; j < 4; ++j) {
                    float* v = d[mt][j];
                    if      (mk0 == 1) { pm[0][2*j] = fmaxf(pm[0][2*j], v[0]); pm[0][2*j+1] = fmaxf(pm[0][2*j+1], v[1]); }
                    else if (mk0 == 2) { pm[1][2*j] = fmaxf(pm[1][2*j], v[0]); pm[1][2*j+1] = fmaxf(pm[1][2*j+1], v[1]); }
                    else if (mk0 == 3) { pm[2][2*j] = fmaxf(pm[2][2*j], v[0]); pm[2][2*j+1] = fmaxf(pm[2][2*j+1], v[1]); }
                    if      (mk1 == 1) { pm[0][2*j] = fmaxf(pm[0][2*j], v[2]); pm[0][2*j+1] = fmaxf(pm[0][2*j+1], v[3]); }
                    else if (mk1 == 2) { pm[1][2*j] = fmaxf(pm[1][2*j], v[2]); pm[1][2*j+1] = fmaxf(pm[1][2*j+1], v[3]); }
                    else if (mk1 == 3) { pm[2][2*j] = fmaxf(pm[2][2*j], v[2]); pm[2][2*j+1] = fmaxf(pm[2][2*j+1], v[3]); }
                }
            }
#pragma unroll
            for (int off = 4; off <= 16; off <<= 1)
#pragma unroll
                for (int m = 0; m < 3; ++m)
#pragma unroll
                    for (int c = 0; c < 8; ++c)
                        pm[m][c] = fmaxf(pm[m][c],
                                         __shfl_xor_sync(0xffffffffu, pm[m][c], off));
            float* red = (float*)(smem + SM_RED);
            if (lane < 4) {
#pragma unroll
                for (int c = 0; c < 8; ++c) {
                    int col = nh * 32 + (c >> 1) * 8 + lane * 2 + (c & 1);
#pragma unroll
                    for (int m = 0; m < 3; ++m)
                        red[(mq * 128 + col) * 3 + m] = pm[m][c];
                }
            }
            asm volatile("bar.sync 1, 512;" ::: "memory");

            if (t < 128 && hok) {
                float* o = out + (size_t)b * (3 * Hn) + (hh * 128 + t) * 3;
#pragma unroll
                for (int m = 0; m < 3; ++m) {
                    float r = fmaxf(fmaxf(red[(0 * 128 + t) * 3 + m],
                                          red[(1 * 128 + t) * 3 + m]),
                                    fmaxf(red[(2 * 128 + t) * 3 + m],
                                          red[(3 * 128 + t) * 3 + m]));
                    o[m] = tanhf(fmaxf(0.f, r + bb));
                }
            }
        } else {
            // ---- producer: stage next unit while GEMM runs ----
            if (u + 1 < NB)
                stage_unit(smem, Xea, Xmask, b + 74, buf ^ 1, t - 512);
        }
        __syncthreads();
    }
}

extern "C" void kernel_launch(void* const* d_in, const int* in_sizes, int n_in,
                              void* d_out, int out_size)
{
    const float* Xea   = (const float*)d_in[0];
    const int*   Xmask = (const int*)  d_in[1];
    const float* W     = (const float*)d_in[2];
    const float* bias  = (const float*)d_in[3];
    float*       out   = (float*)d_out;

    wprep<<<(2 * 128 * WRS + 255) / 256, 256>>>(W);

    cudaFuncSetAttribute(pcnn_mma_kernel,
                         cudaFuncAttributeMaxDynamicSharedMemorySize, SMEM_BYTES);
    dim3 grid(2, 74);
    pcnn_mma_kernel<<<grid, THREADS, SMEM_BYTES>>>(Xea, Xmask, bias, out);
}